// round 2
// baseline (speedup 1.0000x reference)
#include <cuda_runtime.h>
#include <cuda_bf16.h>

#define ETA     0.5f
#define KAPPA   0.1f

// Block reduce helpers -------------------------------------------------------
__device__ __forceinline__ float warp_sum(float v) {
    #pragma unroll
    for (int o = 16; o > 0; o >>= 1)
        v += __shfl_xor_sync(0xFFFFFFFFu, v, o);
    return v;
}

// One CTA per batch row. Reduces:
//   psum = sum_{s,d} pert[b,s,d]^2      (S*D floats)
//   esum = sum_d residue[b,d]^2         (D floats)
//   csum = sum_d cons[b,d]^2            (D floats)
// then thread 0 computes the 4 scalar outputs.
__global__ __launch_bounds__(256, 8)
void soliton_kernel(const float* __restrict__ residue,
                    const float* __restrict__ cons,
                    const float* __restrict__ pert,
                    float* __restrict__ out,
                    int B, int S, int D)
{
    const int b   = blockIdx.x;
    const int tid = threadIdx.x;
    const int nthr = blockDim.x;

    // ---- perturbation row: S*D contiguous floats, float4 vectorized ----
    const float4* __restrict__ p4 =
        reinterpret_cast<const float4*>(pert + (size_t)b * S * D);
    const int n4 = (S * D) >> 2;   // 25600 for S=100, D=1024

    float pacc = 0.0f;
    // Unrolled-by-4 grid-stride: 16 independent loads in flight per thread
    int i = tid;
    #pragma unroll 4
    for (; i + 3 * nthr < n4; i += 4 * nthr) {
        float4 v0 = p4[i];
        float4 v1 = p4[i + nthr];
        float4 v2 = p4[i + 2 * nthr];
        float4 v3 = p4[i + 3 * nthr];
        pacc += v0.x*v0.x + v0.y*v0.y + v0.z*v0.z + v0.w*v0.w;
        pacc += v1.x*v1.x + v1.y*v1.y + v1.z*v1.z + v1.w*v1.w;
        pacc += v2.x*v2.x + v2.y*v2.y + v2.z*v2.z + v2.w*v2.w;
        pacc += v3.x*v3.x + v3.y*v3.y + v3.z*v3.z + v3.w*v3.w;
    }
    for (; i < n4; i += nthr) {
        float4 v = p4[i];
        pacc += v.x*v.x + v.y*v.y + v.z*v.z + v.w*v.w;
    }

    // ---- residue / constraint rows: D floats each ----
    const float4* __restrict__ r4 =
        reinterpret_cast<const float4*>(residue + (size_t)b * D);
    const float4* __restrict__ c4 =
        reinterpret_cast<const float4*>(cons + (size_t)b * D);
    const int d4 = D >> 2;

    float eacc = 0.0f, cacc = 0.0f;
    for (int j = tid; j < d4; j += nthr) {
        float4 rv = r4[j];
        float4 cv = c4[j];
        eacc += rv.x*rv.x + rv.y*rv.y + rv.z*rv.z + rv.w*rv.w;
        cacc += cv.x*cv.x + cv.y*cv.y + cv.z*cv.z + cv.w*cv.w;
    }

    // ---- block reduction of (pacc, eacc, cacc) ----
    __shared__ float sp[8], se[8], sc[8];
    float wp = warp_sum(pacc);
    float we = warp_sum(eacc);
    float wc = warp_sum(cacc);
    const int wid = tid >> 5;
    const int lid = tid & 31;
    if (lid == 0) { sp[wid] = wp; se[wid] = we; sc[wid] = wc; }
    __syncthreads();

    if (tid == 0) {
        float psum = 0.0f, esum = 0.0f, csum = 0.0f;
        const int nw = nthr >> 5;
        #pragma unroll
        for (int w = 0; w < 8; w++) {
            if (w < nw) { psum += sp[w]; esum += se[w]; csum += sc[w]; }
        }

        float dispersion = psum / (float)S;
        float energy     = esum;
        float cscale     = sqrtf(csum);
        float edensity   = energy / (cscale + 1e-8f);
        float loc        = (energy > 0.0f) ? (ETA / (edensity + 1e-8f)) : cscale;
        float ratio      = dispersion / (loc + 1e-8f);

        out[b]         = (ratio < KAPPA) ? 1.0f : 0.0f;  // is_soliton
        out[B + b]     = dispersion;
        out[2 * B + b] = loc;
        out[3 * B + b] = ratio;
    }
}

extern "C" void kernel_launch(void* const* d_in, const int* in_sizes, int n_in,
                              void* d_out, int out_size)
{
    const float* residue = (const float*)d_in[0];
    const float* cons    = (const float*)d_in[1];
    const float* pert    = (const float*)d_in[2];
    float*       out     = (float*)d_out;

    const int D = 1024;
    const int B = in_sizes[0] / D;                 // 1024
    const int S = in_sizes[2] / in_sizes[0];       // 100

    soliton_kernel<<<B, 256>>>(residue, cons, pert, out, B, S, D);
}